// round 16
// baseline (speedup 1.0000x reference)
#include <cuda_runtime.h>
#include <cuda_fp16.h>
#include <cstdint>

// Problem structure constants (fixed by the reference)
#define D_FEAT 128
#define NI     4        // I+1 WL iterations
#define NP     64       // projections
#define NQ     100      // quantiles
#define NC     256      // NI*NP columns
#define NCP    128      // column pairs
#define OUT_PER_G (NI * NQ * NP)   // 25600

#define MAX_N 200192
#define MAX_G 1024
#define MAX_TILES ((MAX_N * 4 + 127) / 128)   // 6256

// Scratch (allocation-free rule: __device__ globals)
__device__ __align__(16) __half2 g_xpT2[(size_t)NCP * MAX_N];  // pair-interleaved projections
__device__ int                   g_starts[MAX_G + 2];
__device__ __align__(16) uint2   g_bfragh[8 * 8 * 32];         // fp16 B frags, m16n8k16
__device__ int                   g_flag[MAX_TILES];            // per-GEMM-tile done flags
__device__ int                   g_task_ctr;                   // sortq task queue head

__device__ __forceinline__ unsigned h2u(__half2 h) { return *reinterpret_cast<unsigned*>(&h); }
__device__ __forceinline__ __half2 u2h2(unsigned u) { return *reinterpret_cast<__half2*>(&u); }

// ---------------------------------------------------------------------------
// Kernel 0a: pack fp16 B fragments for the m16n8k16 MMA.
// ---------------------------------------------------------------------------
__global__ void prep_pack_kernel(const float* __restrict__ proj) {
    int t = blockIdx.x * blockDim.x + threadIdx.x;
    if (t >= 8 * 8 * 32) return;
    int lane = t & 31;
    int tile = t >> 5;          // ks*8 + nt
    int ks   = tile >> 3;
    int nt   = tile & 7;
    int tg   = lane & 3;
    int gg   = lane >> 2;
    int n    = nt * 8 + gg;
    int k0   = ks * 16 + 2 * tg;
    __half2 b0 = __floats2half2_rn(proj[(k0)     * NP + n], proj[(k0 + 1) * NP + n]);
    __half2 b1 = __floats2half2_rn(proj[(k0 + 8) * NP + n], proj[(k0 + 9) * NP + n]);
    g_bfragh[tile * 32 + lane] = make_uint2(h2u(b0), h2u(b1));
}

// ---------------------------------------------------------------------------
// Kernel 0b: segment starts (boundary detection, batch sorted) + flag reset.
// ---------------------------------------------------------------------------
__global__ void prep_starts_kernel(const int* __restrict__ batch, int n, int G,
                                   int mtiles) {
    int t = blockIdx.x * blockDim.x + threadIdx.x;
    if (t < mtiles) g_flag[t] = 0;
    if (t == 0)     g_task_ctr = 0;
    if (t < n) {
        int b    = batch[t];
        int prev = (t == 0) ? -1 : batch[t - 1];
        for (int g = prev + 1; g <= b; g++) g_starts[g] = t;  // covers empty segs
        if (t == n - 1) {
            for (int g = b + 1; g <= G; g++) g_starts[g] = n;
        }
    }
}

// ---------------------------------------------------------------------------
// fp16x2 warp bitonic sort, 256 elements (2 tasks per half2 lane-register).
// Negation-normalized + Batcher-8 front end. Element idx = lane*8 + r.
// ---------------------------------------------------------------------------
__device__ __forceinline__ void cex_asc(__half2& a, __half2& b) {
    __half2 lo = __hmin2(a, b), hi = __hmax2(a, b);
    a = lo; b = hi;
}

__device__ __forceinline__ void bitonic256_h2(__half2 v[8], int lane) {
    const __half2 NEG1 = __float2half2_rn(-1.0f);
    const __half2 POS1 = __float2half2_rn(1.0f);

    {
        __half2 s = (lane & 1) ? NEG1 : POS1;
        #pragma unroll
        for (int r = 0; r < 8; r++) v[r] = __hmul2(v[r], s);
    }
    // Batcher odd-even merge sort of 8 (19 comparators, all ascending)
    cex_asc(v[0], v[1]); cex_asc(v[2], v[3]); cex_asc(v[4], v[5]); cex_asc(v[6], v[7]);
    cex_asc(v[0], v[2]); cex_asc(v[1], v[3]); cex_asc(v[4], v[6]); cex_asc(v[5], v[7]);
    cex_asc(v[1], v[2]); cex_asc(v[5], v[6]);
    cex_asc(v[0], v[4]); cex_asc(v[1], v[5]); cex_asc(v[2], v[6]); cex_asc(v[3], v[7]);
    cex_asc(v[2], v[4]); cex_asc(v[3], v[5]);
    cex_asc(v[1], v[2]); cex_asc(v[3], v[4]); cex_asc(v[5], v[6]);

    int state = lane & 1;
    #pragma unroll
    for (int kk = 1; kk <= 5; kk++) {           // phases k = 16,32,64,128,256
        int want = (kk < 5) ? ((lane >> kk) & 1) : 0;
        __half2 s = (state != want) ? NEG1 : POS1;
        #pragma unroll
        for (int r = 0; r < 8; r++) v[r] = __hmul2(v[r], s);
        state = want;

        #pragma unroll
        for (int lmask = 1 << (kk - 1); lmask >= 1; lmask >>= 1) {
            bool keepmin = ((lane & lmask) == 0);
            #pragma unroll
            for (int r = 0; r < 8; r++) {
                __half2 o = u2h2(__shfl_xor_sync(0xffffffffu, h2u(v[r]), lmask));
                v[r] = keepmin ? __hmin2(v[r], o) : __hmax2(v[r], o);
            }
        }
        cex_asc(v[0], v[4]); cex_asc(v[1], v[5]); cex_asc(v[2], v[6]); cex_asc(v[3], v[7]);
        cex_asc(v[0], v[2]); cex_asc(v[1], v[3]); cex_asc(v[4], v[6]); cex_asc(v[5], v[7]);
        cex_asc(v[0], v[1]); cex_asc(v[2], v[3]); cex_asc(v[4], v[5]); cex_asc(v[6], v[7]);
    }
}

// fp32 variant for the rare big-segment path (n <= 512)
template<int NR>
__device__ __forceinline__ void bitonic_sort_warp(float v[NR], int lane) {
    const int NTOT = NR * 32;
    #pragma unroll
    for (int k = 2; k <= NTOT; k <<= 1) {
        #pragma unroll
        for (int j = k >> 1; j > 0; j >>= 1) {
            if (j < NR) {
                #pragma unroll
                for (int r = 0; r < NR; r++) {
                    if ((r & j) == 0) {
                        int idx = lane * NR + r;
                        bool up = ((idx & k) == 0);
                        float lo = fminf(v[r], v[r | j]);
                        float hi = fmaxf(v[r], v[r | j]);
                        v[r]     = up ? lo : hi;
                        v[r | j] = up ? hi : lo;
                    }
                }
            } else {
                int lmask = j / NR;
                #pragma unroll
                for (int r = 0; r < NR; r++) {
                    int idx = lane * NR + r;
                    float o = __shfl_xor_sync(0xffffffffu, v[r], lmask);
                    bool keepmin = (((idx & k) == 0) == ((idx & j) == 0));
                    v[r] = keepmin ? fminf(v[r], o) : fmaxf(v[r], o);
                }
            }
        }
    }
}

// ---------------------------------------------------------------------------
// FUSED persistent kernel. Grid = nsm*occ (fully resident -> guaranteed
// liveness for any input). Blocks [0, nbg): GEMM workers (grid-stride over
// tiles, publish per-tile flags), then join the sortq task queue. Blocks
// [nbg, grid): sortq workers popping tasks from an atomic queue, spin-waiting
// only on the tile flags covering their segment. GEMM is DRAM-bound and
// sortq is ALU-bound, so co-residency overlaps them on the same SMs.
// ---------------------------------------------------------------------------
#define ASH_STRIDE 136  // halves per row (= 68 words)
#define CS_STRIDE  68

extern "C" __global__ __launch_bounds__(256, 4)
void fused_kernel(const float* __restrict__ x, const float* __restrict__ cw,
                  float* __restrict__ out, int Nn, int G, int mtiles, int nbg) {
    __shared__ __align__(16) char smem[34816];   // GEMM tile buffer / sortq buffers
    __shared__ float scw[NQ];
    __shared__ int   s_bt;

    int tid = threadIdx.x;
    if (tid < NQ) scw[tid] = cw[tid];            // synced before first use below

    const int M = Nn * 4;
    int bid  = blockIdx.x;
    int w    = tid >> 5, lane = tid & 31;

    // ======================= Phase A: GEMM workers =========================
    if (bid < nbg) {
        __half* As_h = reinterpret_cast<__half*>(smem);
        const unsigned* As32 = reinterpret_cast<const unsigned*>(smem);
        float* Cs = reinterpret_cast<float*>(smem);
        int g = lane >> 2, tg = lane & 3;

        for (int tile = bid; tile < mtiles; tile += nbg) {
            int m0 = tile * 128;
            // ---- stage 128x128 fp32 -> fp16 (coalesced LDG.128) ----
            #pragma unroll
            for (int it = 0; it < 16; it++) {
                int idx = tid + it * 256;            // 0..4095 float4 slots
                int row = idx >> 5, c4 = idx & 31;
                int grow = m0 + row;
                if (grow > M - 1) grow = M - 1;
                float4 v = *reinterpret_cast<const float4*>(
                    x + (size_t)grow * D_FEAT + c4 * 4);
                uint2 u;
                u.x = h2u(__floats2half2_rn(v.x, v.y));
                u.y = h2u(__floats2half2_rn(v.z, v.w));
                *reinterpret_cast<uint2*>(&As_h[row * ASH_STRIDE + c4 * 4]) = u;
            }
            __syncthreads();

            // ---- compute: 8 warps x 16-row m-tiles, 8 k-steps of 16 ----
            float acc[8][4];
            #pragma unroll
            for (int i = 0; i < 8; i++)
                #pragma unroll
                for (int j = 0; j < 4; j++) acc[i][j] = 0.f;

            int base0 = (w * 16 + g) * (ASH_STRIDE / 2) + tg;
            #pragma unroll
            for (int ks = 0; ks < 8; ks++) {
                unsigned a0 = As32[base0 + ks * 8];
                unsigned a1 = As32[base0 + 8 * (ASH_STRIDE / 2) + ks * 8];
                unsigned a2 = As32[base0 + ks * 8 + 4];
                unsigned a3 = As32[base0 + 8 * (ASH_STRIDE / 2) + ks * 8 + 4];
                const uint2* bp = g_bfragh + (ks * 8) * 32 + lane;
                #pragma unroll
                for (int nt = 0; nt < 8; nt++) {
                    uint2 bb = bp[nt * 32];
                    asm volatile(
                        "mma.sync.aligned.m16n8k16.row.col.f32.f16.f16.f32 "
                        "{%0,%1,%2,%3}, {%4,%5,%6,%7}, {%8,%9}, {%0,%1,%2,%3};"
                        : "+f"(acc[nt][0]), "+f"(acc[nt][1]),
                          "+f"(acc[nt][2]), "+f"(acc[nt][3])
                        : "r"(a0), "r"(a1), "r"(a2), "r"(a3),
                          "r"(bb.x), "r"(bb.y));
                }
            }
            __syncthreads();   // A reads done before Cs overlay

            #pragma unroll
            for (int nt = 0; nt < 8; nt++) {
                int rl = w * 16 + g;
                int c0 = nt * 8 + tg * 2;
                Cs[rl * CS_STRIDE + c0]            = acc[nt][0];
                Cs[rl * CS_STRIDE + c0 + 1]        = acc[nt][1];
                Cs[(rl + 8) * CS_STRIDE + c0]      = acc[nt][2];
                Cs[(rl + 8) * CS_STRIDE + c0 + 1]  = acc[nt][3];
            }
            __syncthreads();

            // ---- pack half2 pairs: thread = (column pair, row half) ----
            int n0 = m0 >> 2;
            int valid = Nn - n0;
            int cp = tid & 127, rh = tid >> 7;
            int ii = cp >> 5, pp = cp & 31;
            if (valid >= 32 && (Nn & 3) == 0) {
                __half2* dst = g_xpT2 + (size_t)cp * Nn + n0 + rh * 16;
                #pragma unroll
                for (int nl = 0; nl < 16; nl += 4) {
                    int nb = rh * 16 + nl;
                    uint4 u;
                    u.x = h2u(__floats2half2_rn(Cs[((nb + 0) * 4 + ii) * CS_STRIDE + 2 * pp],
                                                Cs[((nb + 0) * 4 + ii) * CS_STRIDE + 2 * pp + 1]));
                    u.y = h2u(__floats2half2_rn(Cs[((nb + 1) * 4 + ii) * CS_STRIDE + 2 * pp],
                                                Cs[((nb + 1) * 4 + ii) * CS_STRIDE + 2 * pp + 1]));
                    u.z = h2u(__floats2half2_rn(Cs[((nb + 2) * 4 + ii) * CS_STRIDE + 2 * pp],
                                                Cs[((nb + 2) * 4 + ii) * CS_STRIDE + 2 * pp + 1]));
                    u.w = h2u(__floats2half2_rn(Cs[((nb + 3) * 4 + ii) * CS_STRIDE + 2 * pp],
                                                Cs[((nb + 3) * 4 + ii) * CS_STRIDE + 2 * pp + 1]));
                    *reinterpret_cast<uint4*>(dst + nl) = u;
                }
            } else {
                int vr = valid < 32 ? valid : 32;
                if (vr < 0) vr = 0;
                int lo = rh * 16;
                int hi = vr < lo + 16 ? vr : lo + 16;
                for (int nl = lo; nl < hi; nl++) {
                    const float* rr = &Cs[(nl * 4 + ii) * CS_STRIDE + 2 * pp];
                    g_xpT2[(size_t)cp * Nn + n0 + nl] = __floats2half2_rn(rr[0], rr[1]);
                }
            }
            __threadfence();       // publish tile data (gpu scope)
            __syncthreads();       // all threads' stores issued+fenced
            if (tid == 0) ((volatile int*)g_flag)[tile] = 1;
            __syncthreads();       // pack reads done before next staging write
        }
    }

    // ================= Phase B: sortq task queue (all blocks) ==============
    {
        __half2 (*sbuf)[256] = reinterpret_cast<__half2 (*)[256]>(smem);       // 8KB
        float   (*qbuf)[NQ]  = reinterpret_cast<float (*)[NQ]>(smem + 8192);   // 6.4KB
        const __half2 hinf = __halves2half2(__ushort_as_half((unsigned short)0x7C00),
                                            __ushort_as_half((unsigned short)0x7C00));
        int ntasks = G * 16;
        while (true) {
            __syncthreads();                       // smem reuse + s_bt safety
            if (tid == 0) s_bt = atomicAdd(&g_task_ctr, 1);
            __syncthreads();
            int bt = s_bt;
            if (bt >= ntasks) break;

            int g  = bt >> 4;
            int s0 = g_starts[g];
            int n  = g_starts[g + 1] - s0;
            if (n > 256) continue;                 // rare path -> sortq_big_kernel

            if (n > 0) {                           // wait for producing tiles
                if (tid == 0) {
                    int t_lo = s0 >> 5;
                    int t_hi = (s0 + n - 1) >> 5;
                    if (t_hi > mtiles - 1) t_hi = mtiles - 1;
                    for (int t = t_lo; t <= t_hi; t++)
                        while (((volatile int*)g_flag)[t] == 0) __nanosleep(64);
                    __threadfence();
                }
                __syncthreads();
            }

            int c0 = (bt & 15) * 16;               // 16 columns of segment g
            int cp = (c0 >> 1) + w;
            const __half2* src = g_xpT2 + (size_t)cp * Nn + s0;

            __half2 v[8];
            #pragma unroll
            for (int r = 0; r < 8; r++) {
                int m = r * 32 + lane;
                v[r] = (m < n) ? __ldg(src + m) : hinf;
            }
            bitonic256_h2(v, lane);
            #pragma unroll
            for (int r = 0; r < 8; r++) sbuf[w][lane * 8 + r] = v[r];
            __syncwarp();

            float nm1 = (float)(n > 0 ? (n - 1) : 0);
            for (int k = lane; k < NQ; k += 32) {
                float vA = 0.f, vB = 0.f;
                if (n > 0) {
                    int qi = (int)floorf(scw[k] * nm1);
                    float2 f = __half22float2(sbuf[w][qi]);
                    vA = f.x * (1.0f / 80.0f);     // scale = (Q*P)^(1/2) = 80
                    vB = f.y * (1.0f / 80.0f);
                }
                qbuf[2 * w][k]     = vA;
                qbuf[2 * w + 1][k] = vB;
            }
            __syncthreads();

            int i0 = c0 >> 6, p0 = c0 & 63;
            float* ob = out + (size_t)g * OUT_PER_G + i0 * (NQ * NP) + p0;
            for (int e = tid; e < NQ * 16; e += 256) {
                int k = e >> 4, pp = e & 15;
                ob[(size_t)k * NP + pp] = qbuf[pp][k];
            }
        }
    }
}

// ---------------------------------------------------------------------------
// Cold path — segments with 256 < n <= 512 (runs after fused kernel).
// ---------------------------------------------------------------------------
__global__ void sortq_big_kernel(const float* __restrict__ cw,
                                 float* __restrict__ out, int Nn) {
    int g  = blockIdx.x;
    int s0 = g_starts[g];
    int n  = g_starts[g + 1] - s0;
    if (n <= 256) return;
    if (n > 512) n = 512;

    __shared__ float sbuf[8][512];
    __shared__ float scw[NQ];
    int tid = threadIdx.x;
    if (tid < NQ) scw[tid] = cw[tid];
    __syncthreads();

    int w = tid >> 5, lane = tid & 31;
    float nm1 = (float)(n - 1);
    for (int c = w; c < NC; c += 8) {
        const __half2* src = g_xpT2 + (size_t)(c >> 1) * Nn + s0;
        int hi = c & 1;
        float v[16];
        #pragma unroll
        for (int r = 0; r < 16; r++) {
            int m = r * 32 + lane;
            if (m < n) {
                __half2 hv = __ldg(src + m);
                v[r] = hi ? __high2float(hv) : __low2float(hv);
            } else {
                v[r] = __int_as_float(0x7f800000);
            }
        }
        bitonic_sort_warp<16>(v, lane);
        #pragma unroll
        for (int r = 0; r < 16; r++) sbuf[w][lane * 16 + r] = v[r];
        __syncwarp();
        int i = c >> 6, p = c & 63;
        float* ob = out + (size_t)g * OUT_PER_G + i * (NQ * NP) + p;
        for (int k = lane; k < NQ; k += 32) {
            int qi = (int)floorf(scw[k] * nm1);
            ob[(size_t)k * NP] = sbuf[w][qi] * (1.0f / 80.0f);
        }
        __syncwarp();
    }
}

// ---------------------------------------------------------------------------
extern "C" void kernel_launch(void* const* d_in, const int* in_sizes, int n_in,
                              void* d_out, int out_size) {
    const float* x     = (const float*)d_in[0];
    const int*   batch = (const int*)d_in[1];
    const float* proj  = (const float*)d_in[2];
    const float* cw    = (const float*)d_in[3];
    float* out = (float*)d_out;

    int Nn = in_sizes[1];
    if (Nn > MAX_N) Nn = MAX_N;
    int G = out_size / OUT_PER_G;
    if (G > MAX_G) G = MAX_G;

    int mtiles = (Nn * 4 + 127) / 128;

    prep_pack_kernel<<<8, 256>>>(proj);

    int cov = Nn > mtiles ? Nn : mtiles;
    int pblocks = (cov + 255) / 256;
    prep_starts_kernel<<<pblocks, 256>>>(batch, Nn, G, mtiles);

    // Fully-resident fused grid (liveness guarantee): nsm * occupancy blocks.
    int dev = 0;
    cudaGetDevice(&dev);
    int nsm = 148;
    cudaDeviceGetAttribute(&nsm, cudaDevAttrMultiProcessorCount, dev);
    int occ = 4;
    cudaOccupancyMaxActiveBlocksPerMultiprocessor(&occ, fused_kernel, 256, 0);
    if (occ < 1) occ = 1;
    if (occ > 4) occ = 4;
    int grid = nsm * occ;
    int nbg  = nsm < grid ? nsm : grid;   // GEMM workers; rest start on sortq

    fused_kernel<<<grid, 256>>>(x, cw, out, Nn, G, mtiles, nbg);

    sortq_big_kernel<<<G, 256>>>(cw, out, Nn);
}

// round 17
// speedup vs baseline: 1.2575x; 1.2575x over previous
#include <cuda_runtime.h>
#include <cuda_fp16.h>
#include <cstdint>

// Problem structure constants (fixed by the reference)
#define D_FEAT 128
#define NI     4        // I+1 WL iterations
#define NP     64       // projections
#define NQ     100      // quantiles
#define NC     256      // NI*NP columns
#define OUT_PER_G (NI * NQ * NP)   // 25600

#define MAX_N 200192
#define MAX_G 1024

// Scratch (allocation-free rule: __device__ globals)
__device__ int                 g_starts[MAX_G + 2];
__device__ __align__(16) uint2 g_bfragh[8 * 8 * 32];   // fp16 B frags, m16n8k16

__device__ __forceinline__ unsigned h2u(__half2 h) { return *reinterpret_cast<unsigned*>(&h); }
__device__ __forceinline__ __half2 u2h2(unsigned u) { return *reinterpret_cast<__half2*>(&u); }

// ---------------------------------------------------------------------------
// Kernel 0a: pack fp16 B fragments for the m16n8k16 MMA (B identical for all
// WL iterations — columns c = i*64+p all use proj[:, p]).
// ---------------------------------------------------------------------------
__global__ void prep_pack_kernel(const float* __restrict__ proj) {
    int t = blockIdx.x * blockDim.x + threadIdx.x;
    if (t >= 8 * 8 * 32) return;
    int lane = t & 31;
    int tile = t >> 5;          // ks*8 + nt
    int ks   = tile >> 3;
    int nt   = tile & 7;
    int tg   = lane & 3;
    int gg   = lane >> 2;
    int n    = nt * 8 + gg;
    int k0   = ks * 16 + 2 * tg;
    __half2 b0 = __floats2half2_rn(proj[(k0)     * NP + n], proj[(k0 + 1) * NP + n]);
    __half2 b1 = __floats2half2_rn(proj[(k0 + 8) * NP + n], proj[(k0 + 9) * NP + n]);
    g_bfragh[tile * 32 + lane] = make_uint2(h2u(b0), h2u(b1));
}

// ---------------------------------------------------------------------------
// Kernel 0b: segment starts via boundary detection (batch sorted).
// ---------------------------------------------------------------------------
__global__ void prep_starts_kernel(const int* __restrict__ batch, int n, int G) {
    int t = blockIdx.x * blockDim.x + threadIdx.x;
    if (t < n) {
        int b    = batch[t];
        int prev = (t == 0) ? -1 : batch[t - 1];
        for (int g = prev + 1; g <= b; g++) g_starts[g] = t;  // covers empty segs
        if (t == n - 1) {
            for (int g = b + 1; g <= G; g++) g_starts[g] = n;
        }
    }
}

// ---------------------------------------------------------------------------
// fp16x2 warp bitonic sort, 256 elements (2 tasks per half2 lane-register).
// Negation-normalized + Batcher-8 front end. Element idx = lane*8 + r.
// ---------------------------------------------------------------------------
__device__ __forceinline__ void cex_asc(__half2& a, __half2& b) {
    __half2 lo = __hmin2(a, b), hi = __hmax2(a, b);
    a = lo; b = hi;
}

__device__ __forceinline__ void bitonic256_h2(__half2 v[8], int lane) {
    const __half2 NEG1 = __float2half2_rn(-1.0f);
    const __half2 POS1 = __float2half2_rn(1.0f);

    {
        __half2 s = (lane & 1) ? NEG1 : POS1;
        #pragma unroll
        for (int r = 0; r < 8; r++) v[r] = __hmul2(v[r], s);
    }
    // Batcher odd-even merge sort of 8 (19 comparators, all ascending)
    cex_asc(v[0], v[1]); cex_asc(v[2], v[3]); cex_asc(v[4], v[5]); cex_asc(v[6], v[7]);
    cex_asc(v[0], v[2]); cex_asc(v[1], v[3]); cex_asc(v[4], v[6]); cex_asc(v[5], v[7]);
    cex_asc(v[1], v[2]); cex_asc(v[5], v[6]);
    cex_asc(v[0], v[4]); cex_asc(v[1], v[5]); cex_asc(v[2], v[6]); cex_asc(v[3], v[7]);
    cex_asc(v[2], v[4]); cex_asc(v[3], v[5]);
    cex_asc(v[1], v[2]); cex_asc(v[3], v[4]); cex_asc(v[5], v[6]);

    int state = lane & 1;
    #pragma unroll
    for (int kk = 1; kk <= 5; kk++) {           // phases k = 16,32,64,128,256
        int want = (kk < 5) ? ((lane >> kk) & 1) : 0;
        __half2 s = (state != want) ? NEG1 : POS1;
        #pragma unroll
        for (int r = 0; r < 8; r++) v[r] = __hmul2(v[r], s);
        state = want;

        #pragma unroll
        for (int lmask = 1 << (kk - 1); lmask >= 1; lmask >>= 1) {
            bool keepmin = ((lane & lmask) == 0);
            #pragma unroll
            for (int r = 0; r < 8; r++) {
                __half2 o = u2h2(__shfl_xor_sync(0xffffffffu, h2u(v[r]), lmask));
                v[r] = keepmin ? __hmin2(v[r], o) : __hmax2(v[r], o);
            }
        }
        cex_asc(v[0], v[4]); cex_asc(v[1], v[5]); cex_asc(v[2], v[6]); cex_asc(v[3], v[7]);
        cex_asc(v[0], v[2]); cex_asc(v[1], v[3]); cex_asc(v[4], v[6]); cex_asc(v[5], v[7]);
        cex_asc(v[0], v[1]); cex_asc(v[2], v[3]); cex_asc(v[4], v[5]); cex_asc(v[6], v[7]);
    }
}

// fp32 variant for the rare big-segment path (n <= 512)
template<int NR>
__device__ __forceinline__ void bitonic_sort_warp(float v[NR], int lane) {
    const int NTOT = NR * 32;
    #pragma unroll
    for (int k = 2; k <= NTOT; k <<= 1) {
        #pragma unroll
        for (int j = k >> 1; j > 0; j >>= 1) {
            if (j < NR) {
                #pragma unroll
                for (int r = 0; r < NR; r++) {
                    if ((r & j) == 0) {
                        int idx = lane * NR + r;
                        bool up = ((idx & k) == 0);
                        float lo = fminf(v[r], v[r | j]);
                        float hi = fmaxf(v[r], v[r | j]);
                        v[r]     = up ? lo : hi;
                        v[r | j] = up ? hi : lo;
                    }
                }
            } else {
                int lmask = j / NR;
                #pragma unroll
                for (int r = 0; r < NR; r++) {
                    int idx = lane * NR + r;
                    float o = __shfl_xor_sync(0xffffffffu, v[r], lmask);
                    bool keepmin = (((idx & k) == 0) == ((idx & j) == 0));
                    v[r] = keepmin ? fminf(v[r], o) : fmaxf(v[r], o);
                }
            }
        }
    }
}

// ---------------------------------------------------------------------------
// FUSED per-(segment, iteration) kernel. Block = (g, i): stages the segment's
// A rows (<=2 chunks of 128x128 fp16), MMA against resident B frags, writes
// C straight from accumulators into smem as half2 column-pairs (stride 264:
// conflict-free STS), then sorts all 32 pairs from smem, gathers quantiles,
// stores. No intermediate DRAM tensor; GEMM (DRAM/tensor) and sort (ALU)
// phases of different blocks overlap naturally on each SM.
// ---------------------------------------------------------------------------
#define ASH_STRIDE 136                 // halves per A row (= 68 words)
#define CSTRIDE    264                 // half2 per C pair row (256 + 8 pad)
#define SM_A       0
#define SM_C       34816               // 128*136*2
#define SM_QB      (34816 + 33792)     // C = 32*264*4
#define SM_CW      (SM_QB + 16 * NQ * 4)
#define SM_TOTAL   (SM_CW + NQ * 4)    // 75408

extern "C" __global__ __launch_bounds__(256)
void seg_kernel(const float* __restrict__ x, const float* __restrict__ cw,
                float* __restrict__ out, int Nn, int G) {
    extern __shared__ __align__(16) char smem[];
    __half*   A    = reinterpret_cast<__half*>(smem + SM_A);
    const unsigned* A32 = reinterpret_cast<const unsigned*>(smem + SM_A);
    __half2*  C    = reinterpret_cast<__half2*>(smem + SM_C);
    float (*qbuf)[NQ] = reinterpret_cast<float (*)[NQ]>(smem + SM_QB);
    float*    scw  = reinterpret_cast<float*>(smem + SM_CW);

    int tid  = threadIdx.x;
    int w    = tid >> 5, lane = tid & 31;
    int g    = blockIdx.x >> 2;
    int ii   = blockIdx.x & 3;

    int s0 = g_starts[g];
    int n  = g_starts[g + 1] - s0;
    if (n > 256) return;                       // cold path handles (block-uniform)

    if (tid < NQ) scw[tid] = cw[tid];

    int gg = lane >> 2, tg = lane & 3;

    // ======================= GEMM into smem C ==============================
    if (n > 0) {
        int nchunks = (n + 127) >> 7;          // 1 or 2
        for (int ch = 0; ch < nchunks; ch++) {
            int base = s0 + ch * 128;
            // ---- stage 128 nodes x 128 cols (iteration ii), fp32 -> fp16 ----
            #pragma unroll
            for (int it = 0; it < 16; it++) {
                int idx = tid + it * 256;      // 4096 float4 slots
                int row = idx >> 5, c4 = idx & 31;
                int node = base + row;
                if (node > Nn - 1) node = Nn - 1;     // rows >= n unused
                float4 v = *reinterpret_cast<const float4*>(
                    x + (size_t)node * (NI * D_FEAT) + ii * D_FEAT + c4 * 4);
                uint2 u;
                u.x = h2u(__floats2half2_rn(v.x, v.y));
                u.y = h2u(__floats2half2_rn(v.z, v.w));
                *reinterpret_cast<uint2*>(&A[row * ASH_STRIDE + c4 * 4]) = u;
            }
            __syncthreads();

            // ---- 8 warps x 16-row m-tiles, 8 k-steps of 16 ----
            float acc[8][4];
            #pragma unroll
            for (int i = 0; i < 8; i++)
                #pragma unroll
                for (int j = 0; j < 4; j++) acc[i][j] = 0.f;

            int base0 = (w * 16 + gg) * (ASH_STRIDE / 2) + tg;
            #pragma unroll
            for (int ks = 0; ks < 8; ks++) {
                unsigned a0 = A32[base0 + ks * 8];
                unsigned a1 = A32[base0 + 8 * (ASH_STRIDE / 2) + ks * 8];
                unsigned a2 = A32[base0 + ks * 8 + 4];
                unsigned a3 = A32[base0 + 8 * (ASH_STRIDE / 2) + ks * 8 + 4];
                const uint2* bp = g_bfragh + (ks * 8) * 32 + lane;
                #pragma unroll
                for (int nt = 0; nt < 8; nt++) {
                    uint2 bb = bp[nt * 32];
                    asm volatile(
                        "mma.sync.aligned.m16n8k16.row.col.f32.f16.f16.f32 "
                        "{%0,%1,%2,%3}, {%4,%5,%6,%7}, {%8,%9}, {%0,%1,%2,%3};"
                        : "+f"(acc[nt][0]), "+f"(acc[nt][1]),
                          "+f"(acc[nt][2]), "+f"(acc[nt][3])
                        : "r"(a0), "r"(a1), "r"(a2), "r"(a3),
                          "r"(bb.x), "r"(bb.y));
                }
            }

            // ---- epilogue: acc pair (cols nt*8+2tg, +1) = C pair nt*4+tg ----
            int node0 = ch * 128 + w * 16 + gg;
            #pragma unroll
            for (int nt = 0; nt < 8; nt++) {
                int pr = nt * 4 + tg;
                C[pr * CSTRIDE + node0]     = __floats2half2_rn(acc[nt][0], acc[nt][1]);
                C[pr * CSTRIDE + node0 + 8] = __floats2half2_rn(acc[nt][2], acc[nt][3]);
            }
            __syncthreads();   // A reads done before restage; C visible at end
        }
    } else {
        __syncthreads();       // scw visibility for the n==0 zero-fill path
    }

    // ================= sort 32 pairs in 4 rounds of 8 warps ================
    const __half2 hinf = __halves2half2(__ushort_as_half((unsigned short)0x7C00),
                                        __ushort_as_half((unsigned short)0x7C00));
    float nm1 = (float)(n > 0 ? (n - 1) : 0);

    for (int t = 0; t < 4; t++) {
        int cp = t * 8 + w;                    // pair -> cols 2cp, 2cp+1
        if (n > 0) {
            __half2 v[8];
            #pragma unroll
            for (int r = 0; r < 8; r++) {
                int m = r * 32 + lane;
                v[r] = (m < n) ? C[cp * CSTRIDE + m] : hinf;
            }
            bitonic256_h2(v, lane);
            #pragma unroll
            for (int r = 0; r < 8; r++) C[cp * CSTRIDE + lane * 8 + r] = v[r];
            __syncwarp();
        }

        // quantile gather (fp32 index rule matches reference bit-exactly)
        for (int k = lane; k < NQ; k += 32) {
            float vA = 0.f, vB = 0.f;
            if (n > 0) {
                int qi = (int)floorf(scw[k] * nm1);
                float2 f = __half22float2(C[cp * CSTRIDE + qi]);
                vA = f.x * (1.0f / 80.0f);     // scale = (Q*P)^(1/2) = 80
                vB = f.y * (1.0f / 80.0f);
            }
            qbuf[2 * w][k]     = vA;
            qbuf[2 * w + 1][k] = vB;
        }
        __syncthreads();

        // cooperative store: 16 consecutive p -> 64B runs per k
        int p0 = t * 16;
        float* ob = out + (size_t)g * OUT_PER_G + ii * (NQ * NP) + p0;
        for (int e = tid; e < NQ * 16; e += 256) {
            int k = e >> 4, pp = e & 15;
            ob[(size_t)k * NP + pp] = qbuf[pp][k];
        }
        __syncthreads();                       // qbuf reuse next round
    }
}

// ---------------------------------------------------------------------------
// Cold path — segments with 256 < n <= 512: compute projections directly
// (fp32 FFMA), sort fp32. Never triggers with this data (R16 profile showed
// all segments n <= 256); correctness-mandatory only.
// ---------------------------------------------------------------------------
__global__ void sortq_big_kernel(const float* __restrict__ x,
                                 const float* __restrict__ proj,
                                 const float* __restrict__ cw,
                                 float* __restrict__ out, int Nn) {
    int g  = blockIdx.x;
    int s0 = g_starts[g];
    int n  = g_starts[g + 1] - s0;
    if (n <= 256) return;
    if (n > 512) n = 512;

    __shared__ float sbuf[8][512];
    __shared__ float scw[NQ];
    int tid = threadIdx.x;
    if (tid < NQ) scw[tid] = cw[tid];
    __syncthreads();

    int w = tid >> 5, lane = tid & 31;
    float nm1 = (float)(n - 1);
    for (int c = w; c < NC; c += 8) {
        int ii = c >> 6, p = c & 63;
        float v[16];
        #pragma unroll
        for (int r = 0; r < 16; r++) {
            int m = r * 32 + lane;
            if (m < n) {
                const float* xr = x + (size_t)(s0 + m) * (NI * D_FEAT) + ii * D_FEAT;
                float s = 0.f;
                for (int d = 0; d < D_FEAT; d++) s += xr[d] * proj[d * NP + p];
                v[r] = s;
            } else {
                v[r] = __int_as_float(0x7f800000);
            }
        }
        bitonic_sort_warp<16>(v, lane);
        #pragma unroll
        for (int r = 0; r < 16; r++) sbuf[w][lane * 16 + r] = v[r];
        __syncwarp();
        float* ob = out + (size_t)g * OUT_PER_G + ii * (NQ * NP) + p;
        for (int k = lane; k < NQ; k += 32) {
            int qi = (int)floorf(scw[k] * nm1);
            ob[(size_t)k * NP] = sbuf[w][qi] * (1.0f / 80.0f);
        }
        __syncwarp();
    }
}

// ---------------------------------------------------------------------------
extern "C" void kernel_launch(void* const* d_in, const int* in_sizes, int n_in,
                              void* d_out, int out_size) {
    const float* x     = (const float*)d_in[0];
    const int*   batch = (const int*)d_in[1];
    const float* proj  = (const float*)d_in[2];
    const float* cw    = (const float*)d_in[3];
    float* out = (float*)d_out;

    int Nn = in_sizes[1];
    if (Nn > MAX_N) Nn = MAX_N;
    int G = out_size / OUT_PER_G;
    if (G > MAX_G) G = MAX_G;

    prep_pack_kernel<<<8, 256>>>(proj);

    int pblocks = (Nn + 255) / 256;
    prep_starts_kernel<<<pblocks, 256>>>(batch, Nn, G);

    static int smem_set = 0;
    if (!smem_set) {
        cudaFuncSetAttribute(seg_kernel,
                             cudaFuncAttributeMaxDynamicSharedMemorySize, SM_TOTAL);
        smem_set = 1;
    }
    seg_kernel<<<G * NI, 256, SM_TOTAL>>>(x, cw, out, Nn, G);

    sortq_big_kernel<<<G, 256>>>(x, proj, cw, out, Nn);
}